// round 11
// baseline (speedup 1.0000x reference)
#include <cuda_runtime.h>
#include <cstdint>

// EfficientSHRFFN — bit-exact semantics (locked in R4, rel_err == 0.0):
//   B=262144, NPOS=4, D=64; opcode=3, OP_START=16 -> op_active idx 19
//   NIB_A=0, NIB_B=1, RESULT=2
//   value f32 sum order: strided halving (t0+t2)+(t1+t3), products exact
//   astype(int64) under x64-disabled jax -> int32, float->int32 SATURATES
//   shifts/byte-extract in int32
//
// R11 change: persistent grid-stride launch (1216 CTAs ~= 152 SMs x 8, one
// wave) over the R10 register-resident row mapping. Theory: ~13 wave
// transitions x ~2360cyc accounted for most of the 11us gap to the 64us
// bandwidth floor; a single persistent wave removes them.

static constexpr long long N_ROWS = 262144;   // B
static constexpr int THREADS      = 256;      // 8 warps per block
static constexpr int BLOCKS       = 1216;     // ~152 SMs * 8 CTAs, one wave
static constexpr long long N_WTASK = N_ROWS / 2;          // 131072 warp-tasks
static constexpr long long W_STRIDE = (long long)BLOCKS * (THREADS / 32); // 9728

__global__ void __launch_bounds__(THREADS)
shrffn_kernel(const float4* __restrict__ in4,
              float4* __restrict__ out4)
{
    const int lane = threadIdx.x & 31;
    const int r    = lane & 15;                       // position within row-half
    const int half = lane >> 4;                       // 0/1: which row of the pair
    long long wtask = (long long)blockIdx.x * (THREADS / 32) + (threadIdx.x >> 5);

    for (; wtask < N_WTASK; wtask += W_STRIDE) {
        const long long row  = wtask * 2 + half;
        const long long base = row * 64 + r;          // float4 index

        // 4 independent 128-bit loads (MLP=4), fully coalesced: per i, each
        // warp-half covers a contiguous 256B span.
        float4 v[4];
#pragma unroll
        for (int i = 0; i < 4; i++) {
            v[i] = in4[base + 16 * i];
        }

        // op_active = element 19 = f4[row*64+4].w, held by lane r==4 of the
        // same warp-half. Broadcast (all lanes participate).
        float op = __shfl_sync(0xffffffffu, v[0].w, (lane & 16) | 4);

        if (r == 0) {
            float a0 = v[0].x;           // in[row*256 + 0]
            float a1 = v[1].x;           // in[row*256 + 64]
            float a2 = v[2].x;           // in[row*256 + 128]
            float a3 = v[3].x;           // in[row*256 + 192]
            float sh_f = v[0].y;         // in[row*256 + 1]

            // Strided-halving tree: (t0+t2) + (t1+t3); products exact.
            float t1 = a1 * 256.0f;
            float t2 = a2 * 65536.0f;
            float t3 = a3 * 16777216.0f;
            float val = __fadd_rn(__fadd_rn(a0, t2), __fadd_rn(t1, t3));

            int value_i = (int)val;      // saturating cvt.rzi.s32.f32

            int shift = (int)sh_f;
            if (shift < 0)  shift = 0;
            if (shift > 31) shift = 31;

            int shifted = value_i >> shift;

#pragma unroll
            for (int p = 0; p < 4; p++) {
                v[p].z = (float)((shifted >> (8 * p)) & 255) * op;
            }
        }

#pragma unroll
        for (int i = 0; i < 4; i++) {
            out4[base + 16 * i] = v[i];
        }
    }
}

extern "C" void kernel_launch(void* const* d_in, const int* in_sizes, int n_in,
                              void* d_out, int out_size)
{
    const float* x = (const float*)d_in[0];
    float* out = (float*)d_out;

    shrffn_kernel<<<BLOCKS, THREADS>>>((const float4*)x, (float4*)out);
}

// round 12
// speedup vs baseline: 1.1249x; 1.1249x over previous
#include <cuda_runtime.h>
#include <cstdint>

// EfficientSHRFFN — bit-exact semantics (locked in R4, rel_err == 0.0):
//   B=262144, NPOS=4, D=64; opcode=3, OP_START=16 -> op_active idx 19
//   NIB_A=0, NIB_B=1, RESULT=2
//   value f32 sum order: strided halving (t0+t2)+(t1+t3), products exact
//   astype(int64) under x64-disabled jax -> int32, float->int32 SATURATES
//   shifts/byte-extract in int32
//
// Perf history (wall / ncu):
//   ITEMS=1 T256        : 84.0 / 81.8
//   ITEMS=4 T256        : 82.1 / 74.6   (.cs hints: 88.8 wall — rejected)
//   ITEMS=8 T256        : 82.4 / 75.9   (occ 49%, rejected)
//   ITEMS=4 T512        : 82.0 / 75.4   (best wall)
//   reg-mapping T256    : 82.7 / 75.2   (lowest issue/alu pressure)
//   persistent 1216 CTAs: 92.3 / 79.4   (scattered frontier — rejected)
// R12: combine the two best traits — register-resident row mapping + T512
// dense launch (grid 8192). Dense CTA frontier preserved, MLP=4/warp.

static constexpr long long N_ROWS = 262144;   // B
static constexpr int THREADS      = 512;      // 16 warps -> 32 rows per block

__global__ void __launch_bounds__(THREADS)
shrffn_kernel(const float4* __restrict__ in4,
              float4* __restrict__ out4)
{
    const int lane = threadIdx.x & 31;
    const int r    = lane & 15;                       // position within row-half
    const long long warp_id = (long long)blockIdx.x * (THREADS / 32)
                            + (threadIdx.x >> 5);
    const long long row  = warp_id * 2 + (lane >> 4); // 2 rows per warp
    const long long base = row * 64 + r;              // float4 index

    // 4 independent 128-bit loads (MLP=4), fully coalesced: per i, each
    // warp-half covers a contiguous 256B span.
    float4 v[4];
#pragma unroll
    for (int i = 0; i < 4; i++) {
        v[i] = in4[base + 16 * i];
    }

    // op_active = element 19 of the row = f4[row*64 + 4].w, held by lane r==4
    // of the same warp-half. Broadcast (all lanes participate).
    float op = __shfl_sync(0xffffffffu, v[0].w, (lane & 16) | 4);

    if (r == 0) {
        // All row inputs are already in registers.
        float a0 = v[0].x;           // in[row*256 + 0]
        float a1 = v[1].x;           // in[row*256 + 64]
        float a2 = v[2].x;           // in[row*256 + 128]
        float a3 = v[3].x;           // in[row*256 + 192]
        float sh_f = v[0].y;         // in[row*256 + 1]

        // Strided-halving tree: (t0+t2) + (t1+t3); products exact.
        float t1 = a1 * 256.0f;
        float t2 = a2 * 65536.0f;
        float t3 = a3 * 16777216.0f;
        float val = __fadd_rn(__fadd_rn(a0, t2), __fadd_rn(t1, t3));

        int value_i = (int)val;      // saturating cvt.rzi.s32.f32

        int shift = (int)sh_f;
        if (shift < 0)  shift = 0;
        if (shift > 31) shift = 31;

        int shifted = value_i >> shift;

#pragma unroll
        for (int p = 0; p < 4; p++) {
            v[p].z = (float)((shifted >> (8 * p)) & 255) * op;
        }
    }

#pragma unroll
    for (int i = 0; i < 4; i++) {
        out4[base + 16 * i] = v[i];
    }
}

extern "C" void kernel_launch(void* const* d_in, const int* in_sizes, int n_in,
                              void* d_out, int out_size)
{
    const float* x = (const float*)d_in[0];
    float* out = (float*)d_out;

    // 2 rows per warp, 16 warps per block -> 32 rows per block
    const int blocks = (int)(N_ROWS / 32);            // 8192, exact division

    shrffn_kernel<<<blocks, THREADS>>>((const float4*)x, (float4*)out);
}

// round 14
// speedup vs baseline: 1.1253x; 1.0004x over previous
#include <cuda_runtime.h>
#include <cstdint>

// EfficientSHRFFN — FINAL. Bit-exact semantics (locked R4, rel_err == 0.0):
//   B=262144, NPOS=4, D=64; opcode=3, OP_START=16 -> op_active idx 19
//   NIB_A=0, NIB_B=1, RESULT=2
//   value f32 sum order: strided halving (t0+t2)+(t1+t3), products exact
//   astype(int64) under x64-disabled jax -> int32, float->int32 SATURATES
//   shifts/byte-extract in int32
//
// Convergence evidence (wall / ncu, DRAM%):
//   ITEMS=1 T256        : 84.0 / 81.8  75.8%
//   ITEMS=4 T256        : 82.1 / 74.6  81.5%   (.cs hints: 88.8 wall — rejected)
//   ITEMS=8 T256        : 82.4 / 75.9  80.1%   (occ 49% — rejected)
//   ITEMS=4 T512        : 82.0 / 75.4  80.8%
//   reg-map  T256       : 82.7 / 75.2  81.0%
//   persistent 1216 CTA : 92.3 / 79.4  77.5%   (scattered frontier — rejected)
//   reg-map  T512 (R12) : 82.0 / 73.9  82.1%   <- winner
// DRAM ~6.5 TB/s is the path-independent LTS/HBM stream ceiling; kernel is
// at the roofline. This round: re-bench of R13 (32-bit indexing) after a
// GB300 container infra failure — no source change warranted by that error.

static constexpr unsigned N_ROWS  = 262144u;  // B
static constexpr int THREADS      = 512;      // 16 warps -> 32 rows per block

__global__ void __launch_bounds__(THREADS)
shrffn_kernel(const float4* __restrict__ in4,
              float4* __restrict__ out4)
{
    const unsigned lane = threadIdx.x & 31u;
    const unsigned r    = lane & 15u;                  // position within row-half
    const unsigned warp_id = blockIdx.x * (THREADS / 32) + (threadIdx.x >> 5);
    const unsigned row  = warp_id * 2u + (lane >> 4);  // 2 rows per warp
    const unsigned base = row * 64u + r;               // float4 index (< 2^24)

    // 4 independent 128-bit loads (MLP=4), fully coalesced: per i, each
    // warp-half covers a contiguous 256B span; warp covers 2KB total.
    float4 v[4];
#pragma unroll
    for (int i = 0; i < 4; i++) {
        v[i] = in4[base + 16u * i];
    }

    // op_active = element 19 of the row = f4[row*64 + 4].w, held by lane r==4
    // of the same warp-half. Broadcast (all lanes participate).
    float op = __shfl_sync(0xffffffffu, v[0].w, (int)((lane & 16u) | 4u));

    if (r == 0u) {
        // All row inputs already in registers.
        float a0 = v[0].x;           // in[row*256 + 0]
        float a1 = v[1].x;           // in[row*256 + 64]
        float a2 = v[2].x;           // in[row*256 + 128]
        float a3 = v[3].x;           // in[row*256 + 192]
        float sh_f = v[0].y;         // in[row*256 + 1]

        // Strided-halving tree: (t0+t2) + (t1+t3); power-of-two products exact.
        float t1 = a1 * 256.0f;
        float t2 = a2 * 65536.0f;
        float t3 = a3 * 16777216.0f;
        float val = __fadd_rn(__fadd_rn(a0, t2), __fadd_rn(t1, t3));

        int value_i = (int)val;      // saturating cvt.rzi.s32.f32

        int shift = (int)sh_f;
        if (shift < 0)  shift = 0;
        if (shift > 31) shift = 31;

        int shifted = value_i >> shift;

#pragma unroll
        for (int p = 0; p < 4; p++) {
            v[p].z = (float)((shifted >> (8 * p)) & 255) * op;
        }
    }

#pragma unroll
    for (int i = 0; i < 4; i++) {
        out4[base + 16u * i] = v[i];
    }
}

extern "C" void kernel_launch(void* const* d_in, const int* in_sizes, int n_in,
                              void* d_out, int out_size)
{
    const float* x = (const float*)d_in[0];
    float* out = (float*)d_out;

    // 2 rows per warp, 16 warps per block -> 32 rows per block
    const int blocks = (int)(N_ROWS / 32u);            // 8192, exact division

    shrffn_kernel<<<blocks, THREADS>>>((const float4*)x, (float4*)out);
}